// round 7
// baseline (speedup 1.0000x reference)
#include <cuda_runtime.h>
#include <cuda_bf16.h>

// ---------------- problem constants ----------------
#define NN      50000
#define EE      800000
#define IN_DIM  128
#define HID     64
#define HEADS   4
#define FW      256          // HEADS*HID
#define OUT_DIM 40
#define NEG     0.2f

// ---------------- device scratch (no allocs allowed) ----------------
__device__ __align__(16) float g_h0[(size_t)NN * HID];        // 12.8 MB
__device__ __align__(16) float g_h [(size_t)NN * FW];         // 51.2 MB
__device__ __align__(16) float g_asrc[(size_t)NN * 4];
__device__ __align__(16) float g_adst[(size_t)NN * 4];
__device__ float g_was[HID * HEADS];
__device__ float g_wad[HID * HEADS];
__device__ int g_cnt[NN + 1];
__device__ int g_cur[NN + 1];
__device__ int g_off[NN + 1];
__device__ int g_csr[EE];
__device__ int g_src[EE];
__device__ int g_dst[EE];
__device__ int g_ts [NN];
__device__ int g_is64;

__device__ __forceinline__ float lrelu(float v) { return v > 0.f ? v : NEG * v; }

// ---------------- dtype detection: int64 indices have zero high words ----------------
__global__ void k_detect(const int* __restrict__ ei_raw) {
    int allzero = 1;
    for (int i = 1; i < 256; i += 2)
        if (ei_raw[i] != 0) { allzero = 0; break; }
    g_is64 = allzero;
}
__global__ void k_cvt_edges(const void* __restrict__ ei, int E) {
    int e = blockIdx.x * blockDim.x + threadIdx.x;
    if (e >= E) return;
    if (g_is64) {
        const long long* p = (const long long*)ei;
        g_src[e] = (int)p[e];
        g_dst[e] = (int)p[(size_t)E + e];
    } else {
        const int* p = (const int*)ei;
        g_src[e] = p[e];
        g_dst[e] = p[(size_t)E + e];
    }
}
__global__ void k_cvt_ts(const void* __restrict__ ts, int N) {
    int n = blockIdx.x * blockDim.x + threadIdx.x;
    if (n >= N) return;
    g_ts[n] = g_is64 ? (int)((const long long*)ts)[n] : ((const int*)ts)[n];
}

// ---------------- 0. fold att vectors into W_gat ----------------
__global__ void k_prep(const float* __restrict__ Wg,
                       const float* __restrict__ att_s,
                       const float* __restrict__ att_d) {
    int t = threadIdx.x;              // 256 threads: k = t>>2, h = t&3
    int k = t >> 2, h = t & 3;
    float s = 0.f, d = 0.f;
    #pragma unroll 8
    for (int c = 0; c < HID; c++) {
        float w = Wg[k * FW + h * HID + c];
        s += w * att_s[h * HID + c];
        d += w * att_d[h * HID + c];
    }
    g_was[t] = s;   // index k*4+h == t
    g_wad[t] = d;
}

// ---------------- 1. h0 = relu(x @ W_proj + b) + temb[ts]   [N,128]x[128,64]
__global__ __launch_bounds__(256) void k_proj(const float* __restrict__ x,
                                              const float* __restrict__ Wp,
                                              const float* __restrict__ bp,
                                              const float* __restrict__ temb,
                                              int N) {
    extern __shared__ float sm[];
    float* Ws = sm;                 // 128*64
    float* Xs = sm + IN_DIM * HID;  // 64*128
    int t = threadIdx.x;
    int row0 = blockIdx.x * 64;
    #pragma unroll
    for (int i = 0; i < 8; i++)
        ((float4*)Ws)[t + 256 * i] = ((const float4*)Wp)[t + 256 * i];
    #pragma unroll
    for (int i = 0; i < 8; i++) {
        int lin = t + 256 * i;
        int r = lin >> 5, c4 = lin & 31;
        float4 v = make_float4(0.f, 0.f, 0.f, 0.f);
        if (row0 + r < N) v = ((const float4*)x)[(size_t)(row0 + r) * 32 + c4];
        ((float4*)Xs)[lin] = v;
    }
    __syncthreads();
    int warp = t >> 5, lane = t & 31;
    float acc0[8] = {0}, acc1[8] = {0};
    #pragma unroll 4
    for (int k = 0; k < IN_DIM; k++) {
        float w0 = Ws[k * HID + lane];
        float w1 = Ws[k * HID + lane + 32];
        #pragma unroll
        for (int r = 0; r < 8; r++) {
            float xv = Xs[(warp * 8 + r) * IN_DIM + k];
            acc0[r] += xv * w0;
            acc1[r] += xv * w1;
        }
    }
    float b0 = bp[lane], b1 = bp[lane + 32];
    #pragma unroll
    for (int r = 0; r < 8; r++) {
        int row = row0 + warp * 8 + r;
        if (row < N) {
            int tt = g_ts[row];
            float v0 = fmaxf(acc0[r] + b0, 0.f) + temb[tt * HID + lane];
            float v1 = fmaxf(acc1[r] + b1, 0.f) + temb[tt * HID + lane + 32];
            g_h0[(size_t)row * HID + lane]      = v0;
            g_h0[(size_t)row * HID + lane + 32] = v1;
        }
    }
}

// ---------------- 2. h = h0 @ W_gat   [N,64]x[64,256]
__global__ __launch_bounds__(256, 2) void k_lin(const float* __restrict__ Wg, int N) {
    extern __shared__ float sm[];
    float* Ws = sm;                 // 64*256 = 16384
    float* Xs = sm + HID * FW;      // 64*64  = 4096
    int t = threadIdx.x;
    int row0 = blockIdx.x * 64;
    #pragma unroll
    for (int i = 0; i < 16; i++)
        ((float4*)Ws)[t + 256 * i] = ((const float4*)Wg)[t + 256 * i];
    #pragma unroll
    for (int i = 0; i < 4; i++) {
        int lin = t + 256 * i;
        int r = lin >> 4, c4 = lin & 15;
        float4 v = make_float4(0.f, 0.f, 0.f, 0.f);
        if (row0 + r < N) v = ((const float4*)g_h0)[(size_t)(row0 + r) * 16 + c4];
        ((float4*)Xs)[lin] = v;
    }
    __syncthreads();
    int warp = t >> 5, lane = t & 31;
    float acc[8][8];
    #pragma unroll
    for (int r = 0; r < 8; r++)
        #pragma unroll
        for (int j = 0; j < 8; j++) acc[r][j] = 0.f;
    #pragma unroll 2
    for (int k = 0; k < HID; k++) {
        float wv[8];
        #pragma unroll
        for (int j = 0; j < 8; j++) wv[j] = Ws[k * FW + lane + 32 * j];
        #pragma unroll
        for (int r = 0; r < 8; r++) {
            float xv = Xs[(warp * 8 + r) * HID + k];
            #pragma unroll
            for (int j = 0; j < 8; j++) acc[r][j] += xv * wv[j];
        }
    }
    #pragma unroll
    for (int r = 0; r < 8; r++) {
        int row = row0 + warp * 8 + r;
        if (row < N) {
            #pragma unroll
            for (int j = 0; j < 8; j++)
                g_h[(size_t)row * FW + lane + 32 * j] = acc[r][j];
        }
    }
}

// ---------------- 3. attention logits per node ----------------
__global__ void k_att(int N) {
    __shared__ float sw[256], sd[256];
    int t = threadIdx.x;
    sw[t] = g_was[t];
    sd[t] = g_wad[t];
    __syncthreads();
    int n = blockIdx.x * blockDim.x + t;
    if (n >= N) return;
    float sa0 = 0, sa1 = 0, sa2 = 0, sa3 = 0;
    float da0 = 0, da1 = 0, da2 = 0, da3 = 0;
    const float4* hp = (const float4*)(g_h0 + (size_t)n * HID);
    #pragma unroll
    for (int k4 = 0; k4 < 16; k4++) {
        float4 hv = hp[k4];
        int k = k4 * 4;
        #define ACC(comp, kk) \
            sa0 += comp * sw[(kk)*4+0]; sa1 += comp * sw[(kk)*4+1]; \
            sa2 += comp * sw[(kk)*4+2]; sa3 += comp * sw[(kk)*4+3]; \
            da0 += comp * sd[(kk)*4+0]; da1 += comp * sd[(kk)*4+1]; \
            da2 += comp * sd[(kk)*4+2]; da3 += comp * sd[(kk)*4+3];
        ACC(hv.x, k + 0) ACC(hv.y, k + 1) ACC(hv.z, k + 2) ACC(hv.w, k + 3)
        #undef ACC
    }
    ((float4*)g_asrc)[n] = make_float4(sa0, sa1, sa2, sa3);
    ((float4*)g_adst)[n] = make_float4(da0, da1, da2, da3);
}

// ---------------- 4. CSR by destination ----------------
__global__ void k_zero(int N) {
    int i = blockIdx.x * blockDim.x + threadIdx.x;
    if (i < N) { g_cnt[i] = 0; g_cur[i] = 0; }
}
__global__ void k_hist(int E) {
    int e = blockIdx.x * blockDim.x + threadIdx.x;
    if (e < E) atomicAdd(&g_cnt[g_dst[e]], 1);
}
__global__ void k_scan(int N) {
    __shared__ int sp[1024];
    int t = threadIdx.x;
    int C = (N + 1023) / 1024;
    int lo = t * C, hi = lo + C; if (hi > N) hi = N; if (lo > N) lo = N;
    int s = 0;
    for (int i = lo; i < hi; i++) s += g_cnt[i];
    sp[t] = s;
    __syncthreads();
    for (int off = 1; off < 1024; off <<= 1) {
        int v = (t >= off) ? sp[t - off] : 0;
        __syncthreads();
        sp[t] += v;
        __syncthreads();
    }
    int run = sp[t] - s;      // exclusive prefix
    for (int i = lo; i < hi; i++) { g_off[i] = run; run += g_cnt[i]; }
    if (t == 1023) g_off[N] = run;
}
__global__ void k_fill(int E) {
    int e = blockIdx.x * blockDim.x + threadIdx.x;
    if (e < E) {
        int d = g_dst[e];
        int pos = g_off[d] + atomicAdd(&g_cur[d], 1);
        g_csr[pos] = g_src[e];
    }
}

// ---------------- 5. fused: per-dst online-softmax gather + relu + classifier ----------------
#define GWARPS 16
#define WC_PAD 10304          // 10240 rounded up past max OOB index 10263
__global__ __launch_bounds__(512) void k_gat(const float* __restrict__ bg,
                                             const float* __restrict__ Wc,
                                             const float* __restrict__ bc,
                                             float* __restrict__ out, int N) {
    extern __shared__ float sm[];
    float* sWc  = sm;                 // WC_PAD floats (10240 used + pad)
    float* rows = sm + WC_PAD;        // GWARPS * 256
    int t = threadIdx.x;
    #pragma unroll
    for (int i = 0; i < 5; i++)
        ((float4*)sWc)[t + 512 * i] = ((const float4*)Wc)[t + 512 * i];
    __syncthreads();
    int warp = t >> 5, lane = t & 31;
    int n = blockIdx.x * GWARPS + warp;
    if (n < N) {
        float4 ad = ((const float4*)g_adst)[n];
        float4 as = ((const float4*)g_asrc)[n];
        // self-loop initializes the online softmax (p = exp(0) = 1)
        float m0 = lrelu(as.x + ad.x), m1 = lrelu(as.y + ad.y);
        float m2 = lrelu(as.z + ad.z), m3 = lrelu(as.w + ad.w);
        float d0 = 1.f, d1 = 1.f, d2 = 1.f, d3 = 1.f;
        float acc[8];
        const float* hp = g_h + (size_t)n * FW + lane;
        #pragma unroll
        for (int k = 0; k < 8; k++) acc[k] = hp[32 * k];
        int beg = g_off[n], end = g_off[n + 1];
        for (int i = beg; i < end; i++) {
            int s = g_csr[i];                       // warp-uniform broadcast load
            float4 a = ((const float4*)g_asrc)[s];
            float e0 = lrelu(a.x + ad.x), e1 = lrelu(a.y + ad.y);
            float e2 = lrelu(a.z + ad.z), e3 = lrelu(a.w + ad.w);
            if (e0 > m0 || e1 > m1 || e2 > m2 || e3 > m3) {  // warp-uniform rescale
                float n0 = fmaxf(m0, e0), n1 = fmaxf(m1, e1);
                float n2 = fmaxf(m2, e2), n3 = fmaxf(m3, e3);
                float s0 = __expf(m0 - n0), s1 = __expf(m1 - n1);
                float s2 = __expf(m2 - n2), s3 = __expf(m3 - n3);
                d0 *= s0; d1 *= s1; d2 *= s2; d3 *= s3;
                acc[0] *= s0; acc[1] *= s0; acc[2] *= s1; acc[3] *= s1;
                acc[4] *= s2; acc[5] *= s2; acc[6] *= s3; acc[7] *= s3;
                m0 = n0; m1 = n1; m2 = n2; m3 = n3;
            }
            float p0 = __expf(e0 - m0), p1 = __expf(e1 - m1);
            float p2 = __expf(e2 - m2), p3 = __expf(e3 - m3);
            d0 += p0; d1 += p1; d2 += p2; d3 += p3;
            const float* hq = g_h + (size_t)s * FW + lane;
            acc[0] += p0 * hq[0];   acc[1] += p0 * hq[32];
            acc[2] += p1 * hq[64];  acc[3] += p1 * hq[96];
            acc[4] += p2 * hq[128]; acc[5] += p2 * hq[160];
            acc[6] += p3 * hq[192]; acc[7] += p3 * hq[224];
        }
        float r0 = 1.f / (d0 + 1e-16f), r1 = 1.f / (d1 + 1e-16f);
        float r2 = 1.f / (d2 + 1e-16f), r3 = 1.f / (d3 + 1e-16f);
        float* rb = rows + warp * 256;
        rb[lane]       = fmaxf(acc[0] * r0 + bg[lane],       0.f);
        rb[lane + 32]  = fmaxf(acc[1] * r0 + bg[lane + 32],  0.f);
        rb[lane + 64]  = fmaxf(acc[2] * r1 + bg[lane + 64],  0.f);
        rb[lane + 96]  = fmaxf(acc[3] * r1 + bg[lane + 96],  0.f);
        rb[lane + 128] = fmaxf(acc[4] * r2 + bg[lane + 128], 0.f);
        rb[lane + 160] = fmaxf(acc[5] * r2 + bg[lane + 160], 0.f);
        rb[lane + 192] = fmaxf(acc[6] * r3 + bg[lane + 192], 0.f);
        rb[lane + 224] = fmaxf(acc[7] * r3 + bg[lane + 224], 0.f);
    }
    __syncwarp();
    if (n < N) {
        float o0 = bc[lane];
        float o1 = (lane < 8) ? bc[lane + 32] : 0.f;
        const float* rb = rows + warp * 256;
        #pragma unroll 8
        for (int i = 0; i < 256; i++) {
            float av = rb[i];
            o0 += av * sWc[i * 40 + lane];
            o1 += av * sWc[i * 40 + lane + 32];   // pad keeps lane>=8 reads in-bounds
        }
        out[(size_t)n * OUT_DIM + lane] = o0;
        if (lane < 8) out[(size_t)n * OUT_DIM + 32 + lane] = o1;
    }
}

// ---------------- launch ----------------
extern "C" void kernel_launch(void* const* d_in, const int* in_sizes, int n_in,
                              void* d_out, int out_size) {
    const float* x    = (const float*)d_in[0];
    const void*  ei   = d_in[1];
    const void*  ts   = d_in[2];
    const float* Wp   = (const float*)d_in[3];
    const float* bp   = (const float*)d_in[4];
    const float* temb = (const float*)d_in[5];
    const float* Wg   = (const float*)d_in[6];
    const float* atts = (const float*)d_in[7];
    const float* attd = (const float*)d_in[8];
    const float* bg   = (const float*)d_in[9];
    const float* Wc   = (const float*)d_in[10];
    const float* bc   = (const float*)d_in[11];
    float* out = (float*)d_out;

    int N = in_sizes[0] / IN_DIM;   // 50000
    int E = in_sizes[1] / 2;        // 800000

    size_t sm_proj = (size_t)(IN_DIM * HID + 64 * IN_DIM) * 4;   // 64 KB
    size_t sm_lin  = (size_t)(HID * FW + 64 * HID) * 4;          // 80 KB
    size_t sm_gat  = (size_t)(WC_PAD + GWARPS * 256) * 4;        // ~56 KB
    cudaFuncSetAttribute(k_proj, cudaFuncAttributeMaxDynamicSharedMemorySize, (int)sm_proj);
    cudaFuncSetAttribute(k_lin,  cudaFuncAttributeMaxDynamicSharedMemorySize, (int)sm_lin);
    cudaFuncSetAttribute(k_gat,  cudaFuncAttributeMaxDynamicSharedMemorySize, (int)sm_gat);

    k_detect<<<1, 1>>>((const int*)ei);
    k_cvt_edges<<<(E + 255) / 256, 256>>>(ei, E);
    k_cvt_ts<<<(N + 255) / 256, 256>>>(ts, N);
    k_prep<<<1, 256>>>(Wg, atts, attd);
    k_proj<<<(N + 63) / 64, 256, sm_proj>>>(x, Wp, bp, temb, N);
    k_lin <<<(N + 63) / 64, 256, sm_lin>>>(Wg, N);
    k_att <<<(N + 255) / 256, 256>>>(N);
    k_zero<<<(N + 255) / 256, 256>>>(N);
    k_hist<<<(E + 255) / 256, 256>>>(E);
    k_scan<<<1, 1024>>>(N);
    k_fill<<<(E + 255) / 256, 256>>>(E);
    k_gat <<<(N + GWARPS - 1) / GWARPS, 512, sm_gat>>>(bg, Wc, bc, out, N);
}

// round 11
// speedup vs baseline: 1.2257x; 1.2257x over previous
#include <cuda_runtime.h>
#include <cuda_bf16.h>

// ---------------- problem constants ----------------
#define NN      50000
#define EE      800000
#define IN_DIM  128
#define HID     64
#define HEADS   4
#define FW      256          // HEADS*HID
#define OUT_DIM 40
#define NEG     0.2f

// ---------------- device scratch (no allocs allowed) ----------------
__device__ __align__(16) float g_h0[(size_t)NN * HID];        // 12.8 MB
__device__ __align__(16) float g_h [(size_t)NN * FW];         // 51.2 MB
__device__ __align__(16) float g_go[(size_t)NN * FW];         // 51.2 MB relu(gat_out)
__device__ __align__(16) float g_asrc[(size_t)NN * 4];
__device__ __align__(16) float g_adst[(size_t)NN * 4];
__device__ int g_cnt[NN + 1];
__device__ int g_cur[NN + 1];
__device__ int g_off[NN + 1];
__device__ int g_csr[EE];
__device__ int g_src[EE];
__device__ int g_ts [NN];
__device__ int g_is64;

__device__ __forceinline__ float lrelu(float v) { return v > 0.f ? v : NEG * v; }

// ---------------- A. zero counters + dtype detection ----------------
__global__ void k_init(const int* __restrict__ ei_raw, int N) {
    int i = blockIdx.x * blockDim.x + threadIdx.x;
    if (i < N) { g_cnt[i] = 0; g_cur[i] = 0; }
    if (blockIdx.x == 0 && threadIdx.x == 0) {
        int allzero = 1;
        for (int k = 1; k < 256; k += 2)
            if (ei_raw[k] != 0) { allzero = 0; break; }
        g_is64 = allzero;
    }
}

// ---------------- B. convert edges + histogram + timesteps ----------------
__global__ void k_cvt(const void* __restrict__ ei, const void* __restrict__ ts,
                      int E, int N) {
    int e = blockIdx.x * blockDim.x + threadIdx.x;
    int is64 = g_is64;
    if (e < E) {
        int s, d;
        if (is64) {
            const long long* p = (const long long*)ei;
            s = (int)p[e];
            d = (int)p[(size_t)E + e];
        } else {
            const int* p = (const int*)ei;
            s = p[e];
            d = p[(size_t)E + e];
        }
        g_src[e] = s;
        atomicAdd(&g_cnt[d], 1);
    }
    if (e < N)
        g_ts[e] = is64 ? (int)((const long long*)ts)[e] : ((const int*)ts)[e];
}

// ---------------- 1. h0 = relu(x @ W_proj + b) + temb[ts]   [N,128]x[128,64]
__global__ __launch_bounds__(256) void k_proj(const float* __restrict__ x,
                                              const float* __restrict__ Wp,
                                              const float* __restrict__ bp,
                                              const float* __restrict__ temb,
                                              int N) {
    extern __shared__ float sm[];
    float* Ws = sm;                 // 128*64
    float* Xs = sm + IN_DIM * HID;  // 64*128
    int t = threadIdx.x;
    int row0 = blockIdx.x * 64;
    #pragma unroll
    for (int i = 0; i < 8; i++)
        ((float4*)Ws)[t + 256 * i] = ((const float4*)Wp)[t + 256 * i];
    #pragma unroll
    for (int i = 0; i < 8; i++) {
        int lin = t + 256 * i;
        int r = lin >> 5, c4 = lin & 31;
        float4 v = make_float4(0.f, 0.f, 0.f, 0.f);
        if (row0 + r < N) v = ((const float4*)x)[(size_t)(row0 + r) * 32 + c4];
        ((float4*)Xs)[lin] = v;
    }
    __syncthreads();
    int warp = t >> 5, lane = t & 31;
    float acc0[8] = {0}, acc1[8] = {0};
    #pragma unroll 4
    for (int k = 0; k < IN_DIM; k++) {
        float w0 = Ws[k * HID + lane];
        float w1 = Ws[k * HID + lane + 32];
        #pragma unroll
        for (int r = 0; r < 8; r++) {
            float xv = Xs[(warp * 8 + r) * IN_DIM + k];
            acc0[r] += xv * w0;
            acc1[r] += xv * w1;
        }
    }
    float b0 = bp[lane], b1 = bp[lane + 32];
    #pragma unroll
    for (int r = 0; r < 8; r++) {
        int row = row0 + warp * 8 + r;
        if (row < N) {
            int tt = g_ts[row];
            float v0 = fmaxf(acc0[r] + b0, 0.f) + temb[tt * HID + lane];
            float v1 = fmaxf(acc1[r] + b1, 0.f) + temb[tt * HID + lane + 32];
            g_h0[(size_t)row * HID + lane]      = v0;
            g_h0[(size_t)row * HID + lane + 32] = v1;
        }
    }
}

// ---------------- 2. h = h0 @ W_gat  [N,64]x[64,256]  + fused attention logits
__global__ __launch_bounds__(256, 2) void k_lin(const float* __restrict__ Wg,
                                                const float* __restrict__ att_s,
                                                const float* __restrict__ att_d,
                                                int N) {
    extern __shared__ float sm[];
    float* Ws = sm;                 // 64*256 = 16384
    float* Xs = sm + HID * FW;      // 64*64  = 4096
    int t = threadIdx.x;
    int row0 = blockIdx.x * 64;
    #pragma unroll
    for (int i = 0; i < 16; i++)
        ((float4*)Ws)[t + 256 * i] = ((const float4*)Wg)[t + 256 * i];
    #pragma unroll
    for (int i = 0; i < 4; i++) {
        int lin = t + 256 * i;
        int r = lin >> 4, c4 = lin & 15;
        float4 v = make_float4(0.f, 0.f, 0.f, 0.f);
        if (row0 + r < N) v = ((const float4*)g_h0)[(size_t)(row0 + r) * 16 + c4];
        ((float4*)Xs)[lin] = v;
    }
    __syncthreads();
    int warp = t >> 5, lane = t & 31;
    float acc[8][8];
    #pragma unroll
    for (int r = 0; r < 8; r++)
        #pragma unroll
        for (int j = 0; j < 8; j++) acc[r][j] = 0.f;
    #pragma unroll 2
    for (int k = 0; k < HID; k++) {
        float wv[8];
        #pragma unroll
        for (int j = 0; j < 8; j++) wv[j] = Ws[k * FW + lane + 32 * j];
        #pragma unroll
        for (int r = 0; r < 8; r++) {
            float xv = Xs[(warp * 8 + r) * HID + k];
            #pragma unroll
            for (int j = 0; j < 8; j++) acc[r][j] += xv * wv[j];
        }
    }
    // att coefficients for this thread's 8 columns (col = lane + 32j, flat index == att index)
    float av[8], dv[8];
    #pragma unroll
    for (int j = 0; j < 8; j++) {
        av[j] = att_s[lane + 32 * j];
        dv[j] = att_d[lane + 32 * j];
    }
    #pragma unroll
    for (int r = 0; r < 8; r++) {
        int row = row0 + warp * 8 + r;
        bool ok = row < N;
        if (ok) {
            #pragma unroll
            for (int j = 0; j < 8; j++)
                g_h[(size_t)row * FW + lane + 32 * j] = acc[r][j];
        }
        // per-head partial sums: head h uses j in {2h, 2h+1}
        float s0 = acc[r][0] * av[0] + acc[r][1] * av[1];
        float s1 = acc[r][2] * av[2] + acc[r][3] * av[3];
        float s2 = acc[r][4] * av[4] + acc[r][5] * av[5];
        float s3 = acc[r][6] * av[6] + acc[r][7] * av[7];
        float d0 = acc[r][0] * dv[0] + acc[r][1] * dv[1];
        float d1 = acc[r][2] * dv[2] + acc[r][3] * dv[3];
        float d2 = acc[r][4] * dv[4] + acc[r][5] * dv[5];
        float d3 = acc[r][6] * dv[6] + acc[r][7] * dv[7];
        #pragma unroll
        for (int off = 16; off > 0; off >>= 1) {
            s0 += __shfl_xor_sync(0xffffffffu, s0, off);
            s1 += __shfl_xor_sync(0xffffffffu, s1, off);
            s2 += __shfl_xor_sync(0xffffffffu, s2, off);
            s3 += __shfl_xor_sync(0xffffffffu, s3, off);
            d0 += __shfl_xor_sync(0xffffffffu, d0, off);
            d1 += __shfl_xor_sync(0xffffffffu, d1, off);
            d2 += __shfl_xor_sync(0xffffffffu, d2, off);
            d3 += __shfl_xor_sync(0xffffffffu, d3, off);
        }
        if (ok && lane == 0) {
            ((float4*)g_asrc)[row] = make_float4(s0, s1, s2, s3);
            ((float4*)g_adst)[row] = make_float4(d0, d1, d2, d3);
        }
    }
}

// ---------------- 4. CSR by destination ----------------
__global__ void k_scan(int N) {
    __shared__ int sp[1024];
    int t = threadIdx.x;
    int C = (N + 1023) / 1024;
    int lo = t * C, hi = lo + C; if (hi > N) hi = N; if (lo > N) lo = N;
    int s = 0;
    for (int i = lo; i < hi; i++) s += g_cnt[i];
    sp[t] = s;
    __syncthreads();
    for (int off = 1; off < 1024; off <<= 1) {
        int v = (t >= off) ? sp[t - off] : 0;
        __syncthreads();
        sp[t] += v;
        __syncthreads();
    }
    int run = sp[t] - s;      // exclusive prefix
    for (int i = lo; i < hi; i++) { g_off[i] = run; run += g_cnt[i]; }
    if (t == 1023) g_off[N] = run;
}
__global__ void k_fill(const void* __restrict__ ei, int E) {
    int e = blockIdx.x * blockDim.x + threadIdx.x;
    if (e < E) {
        int d = g_is64 ? (int)((const long long*)ei)[(size_t)E + e]
                       : ((const int*)ei)[(size_t)E + e];
        int pos = g_off[d] + atomicAdd(&g_cur[d], 1);
        g_csr[pos] = g_src[e];
    }
}

// ---------------- 5. per-dst online-softmax gather -> g_go (relu'd, + b_gat) ----------------
__global__ __launch_bounds__(256) void k_gat(const float* __restrict__ bg, int N) {
    int t = threadIdx.x;
    int warp = t >> 5, lane = t & 31;
    int n = blockIdx.x * 8 + warp;
    if (n >= N) return;
    const float4* asrc4 = (const float4*)g_asrc;
    float4 ad = ((const float4*)g_adst)[n];
    float4 as = asrc4[n];
    // self-loop initializes online softmax (p = exp(0) = 1)
    float m0 = lrelu(as.x + ad.x), m1 = lrelu(as.y + ad.y);
    float m2 = lrelu(as.z + ad.z), m3 = lrelu(as.w + ad.w);
    float d0 = 1.f, d1 = 1.f, d2 = 1.f, d3 = 1.f;
    // lane covers cols 4*lane..4*lane+3 (chunk0: heads 0/1) and +128 (chunk1: heads 2/3)
    const float4* hself = (const float4*)(g_h + (size_t)n * FW);
    float4 acc0 = hself[lane];
    float4 acc1 = hself[lane + 32];
    bool lo = lane < 16;

    int beg = g_off[n], end = g_off[n + 1];
    int i = beg;
    int sN = 0; float4 aN = make_float4(0.f, 0.f, 0.f, 0.f);
    if (i < end) { sN = g_csr[i]; aN = asrc4[sN]; }
    while (i < end) {
        int s = sN; float4 a = aN;
        const float4* hq = (const float4*)(g_h + (size_t)s * FW);
        float4 hA = hq[lane];
        float4 hB = hq[lane + 32];
        int j = i + 1;
        if (j < end) { sN = g_csr[j]; aN = asrc4[sN]; }
        float e0 = lrelu(a.x + ad.x), e1 = lrelu(a.y + ad.y);
        float e2 = lrelu(a.z + ad.z), e3 = lrelu(a.w + ad.w);
        if (e0 > m0 || e1 > m1 || e2 > m2 || e3 > m3) {   // warp-uniform
            float n0 = fmaxf(m0, e0), n1 = fmaxf(m1, e1);
            float n2 = fmaxf(m2, e2), n3 = fmaxf(m3, e3);
            float s0 = __expf(m0 - n0), s1 = __expf(m1 - n1);
            float s2 = __expf(m2 - n2), s3 = __expf(m3 - n3);
            d0 *= s0; d1 *= s1; d2 *= s2; d3 *= s3;
            float sa = lo ? s0 : s1, sb = lo ? s2 : s3;
            acc0.x *= sa; acc0.y *= sa; acc0.z *= sa; acc0.w *= sa;
            acc1.x *= sb; acc1.y *= sb; acc1.z *= sb; acc1.w *= sb;
            m0 = n0; m1 = n1; m2 = n2; m3 = n3;
        }
        float p0 = __expf(e0 - m0), p1 = __expf(e1 - m1);
        float p2 = __expf(e2 - m2), p3 = __expf(e3 - m3);
        d0 += p0; d1 += p1; d2 += p2; d3 += p3;
        float pa = lo ? p0 : p1, pb = lo ? p2 : p3;
        acc0.x += pa * hA.x; acc0.y += pa * hA.y; acc0.z += pa * hA.z; acc0.w += pa * hA.w;
        acc1.x += pb * hB.x; acc1.y += pb * hB.y; acc1.z += pb * hB.z; acc1.w += pb * hB.w;
        i = j;
    }
    float r0 = 1.f / (d0 + 1e-16f), r1 = 1.f / (d1 + 1e-16f);
    float r2 = 1.f / (d2 + 1e-16f), r3 = 1.f / (d3 + 1e-16f);
    float ra = lo ? r0 : r1, rb = lo ? r2 : r3;
    float4 bgA = ((const float4*)bg)[lane];
    float4 bgB = ((const float4*)bg)[lane + 32];
    float4 o0, o1;
    o0.x = fmaxf(acc0.x * ra + bgA.x, 0.f);
    o0.y = fmaxf(acc0.y * ra + bgA.y, 0.f);
    o0.z = fmaxf(acc0.z * ra + bgA.z, 0.f);
    o0.w = fmaxf(acc0.w * ra + bgA.w, 0.f);
    o1.x = fmaxf(acc1.x * rb + bgB.x, 0.f);
    o1.y = fmaxf(acc1.y * rb + bgB.y, 0.f);
    o1.z = fmaxf(acc1.z * rb + bgB.z, 0.f);
    o1.w = fmaxf(acc1.w * rb + bgB.w, 0.f);
    ((float4*)(g_go + (size_t)n * FW))[lane]      = o0;
    ((float4*)(g_go + (size_t)n * FW))[lane + 32] = o1;
}

// ---------------- 6. classifier GEMM: out = g_go @ Wc + bc  [N,256]x[256,40]
#define KP 260   // padded K stride (bank-spread, divisible by 4)
__global__ __launch_bounds__(256, 2) void k_cls(const float* __restrict__ Wc,
                                                const float* __restrict__ bc,
                                                float* __restrict__ out, int N) {
    extern __shared__ float sm[];
    float* sW = sm;               // [40][KP] transposed Wc
    float* sA = sm + 40 * KP;     // [64][KP]
    int t = threadIdx.x;
    int row0 = blockIdx.x * 64;
    // load + transpose Wc (coalesced read)
    for (int idx = t; idx < FW * OUT_DIM; idx += 256) {
        int k = idx / OUT_DIM, c = idx % OUT_DIM;
        sW[c * KP + k] = Wc[idx];
    }
    // load A tile (float4)
    #pragma unroll
    for (int i = 0; i < 16; i++) {
        int lin = t + 256 * i;          // 4096 float4 slots
        int r = lin >> 6, c4 = lin & 63;
        float4 v = make_float4(0.f, 0.f, 0.f, 0.f);
        if (row0 + r < N) v = ((const float4*)g_go)[(size_t)(row0 + r) * 64 + c4];
        *(float4*)(sA + r * KP + c4 * 4) = v;
    }
    __syncthreads();
    int colg = t & 7;        // 8 column groups x 5 cols
    int rp   = t >> 3;       // 32 row pairs
    const float* a0p = sA + (rp * 2) * KP;
    const float* a1p = sA + (rp * 2 + 1) * KP;
    float acc0[5] = {0}, acc1[5] = {0};
    #pragma unroll 4
    for (int k4 = 0; k4 < 64; k4++) {
        float4 a0 = ((const float4*)a0p)[k4];
        float4 a1 = ((const float4*)a1p)[k4];
        #pragma unroll
        for (int i = 0; i < 5; i++) {
            float4 w = ((const float4*)(sW + (colg * 5 + i) * KP))[k4];
            acc0[i] += a0.x * w.x + a0.y * w.y + a0.z * w.z + a0.w * w.w;
            acc1[i] += a1.x * w.x + a1.y * w.y + a1.z * w.z + a1.w * w.w;
        }
    }
    int r0 = row0 + rp * 2, r1 = r0 + 1;
    #pragma unroll
    for (int i = 0; i < 5; i++) {
        int c = colg * 5 + i;
        float b = bc[c];
        if (r0 < N) out[(size_t)r0 * OUT_DIM + c] = acc0[i] + b;
        if (r1 < N) out[(size_t)r1 * OUT_DIM + c] = acc1[i] + b;
    }
}

// ---------------- launch ----------------
extern "C" void kernel_launch(void* const* d_in, const int* in_sizes, int n_in,
                              void* d_out, int out_size) {
    const float* x    = (const float*)d_in[0];
    const void*  ei   = d_in[1];
    const void*  ts   = d_in[2];
    const float* Wp   = (const float*)d_in[3];
    const float* bp   = (const float*)d_in[4];
    const float* temb = (const float*)d_in[5];
    const float* Wg   = (const float*)d_in[6];
    const float* atts = (const float*)d_in[7];
    const float* attd = (const float*)d_in[8];
    const float* bg   = (const float*)d_in[9];
    const float* Wc   = (const float*)d_in[10];
    const float* bc   = (const float*)d_in[11];
    float* out = (float*)d_out;

    int N = in_sizes[0] / IN_DIM;   // 50000
    int E = in_sizes[1] / 2;        // 800000

    size_t sm_proj = (size_t)(IN_DIM * HID + 64 * IN_DIM) * 4;   // 64 KB
    size_t sm_lin  = (size_t)(HID * FW + 64 * HID) * 4;          // 80 KB
    size_t sm_cls  = (size_t)(40 * KP + 64 * KP) * 4;            // ~106 KB
    cudaFuncSetAttribute(k_proj, cudaFuncAttributeMaxDynamicSharedMemorySize, (int)sm_proj);
    cudaFuncSetAttribute(k_lin,  cudaFuncAttributeMaxDynamicSharedMemorySize, (int)sm_lin);
    cudaFuncSetAttribute(k_cls,  cudaFuncAttributeMaxDynamicSharedMemorySize, (int)sm_cls);

    k_init<<<(N + 255) / 256, 256>>>((const int*)ei, N);
    k_cvt <<<(E + 255) / 256, 256>>>(ei, ts, E, N);
    k_proj<<<(N + 63) / 64, 256, sm_proj>>>(x, Wp, bp, temb, N);
    k_lin <<<(N + 63) / 64, 256, sm_lin>>>(Wg, atts, attd, N);
    k_scan<<<1, 1024>>>(N);
    k_fill<<<(E + 255) / 256, 256>>>(ei, E);
    k_gat <<<(N + 7) / 8, 256>>>(bg, N);
    k_cls <<<(N + 63) / 64, 256, sm_cls>>>(Wc, bc, out, N);
}